// round 3
// baseline (speedup 1.0000x reference)
#include <cuda_runtime.h>
#include <math.h>

// Problem constants
#define LSIG     524288
#define NFFT     1024
#define NC       512          // complex FFT size (rfft-via-cfft trick)
#define HOP      256
#define NFRAMES  2049
#define NB       32
#define FOUT     512          // freq bins 1..512
#define TOUT     2048         // frames 1..2048

// fp64-accurate tables (filled by init kernel each launch; deterministic)
__device__ float  d_win[NFFT];
__device__ float2 d_tw[256];     // exp(-2*pi*i*k/512), k=0..255
__device__ float2 d_unt[513];    // C_k = -i*exp(-i*pi*k/512) = (-sin, -cos)
// complex spectrum scratch, frame-major: [b][t][k-1], k=1..512  (268 MB)
__device__ float2 d_spec[(size_t)NB * NFRAMES * FOUT];

__global__ void init_tables_kernel() {
    int i = threadIdx.x;                      // 1024 threads
    const double PI = 3.14159265358979323846;
    d_win[i] = (float)(0.5 * (1.0 - cos(2.0 * PI * (double)i / 1024.0)));
    if (i < 256) {
        double th = -2.0 * PI * (double)i / 512.0;
        d_tw[i] = make_float2((float)cos(th), (float)sin(th));
    }
    if (i < 513) {
        double th = PI * (double)i / 512.0;
        d_unt[i] = make_float2((float)(-sin(th)), (float)(-cos(th)));
    }
}

// One CTA = one frame (b, t). 256 threads, 512-pt complex radix-2 FFT in smem.
// Writes the rFFT bins k=1..512 (complex) to frame-major scratch, coalesced.
__global__ __launch_bounds__(256) void stft_frame_kernel(const float* __restrict__ x)
{
    __shared__ float2 s[NC];
    const int t   = blockIdx.x;     // 0..2048
    const int b   = blockIdx.y;     // 0..31
    const int tid = threadIdx.x;    // 0..255

    const float* xb = x + (size_t)b * LSIG;
    const int base = t * HOP - (NFFT / 2);   // padded start - pad

    // Load 2 complex points (4 real samples) w/ reflect pad + window,
    // stored bit-reversed for DIT.
    #pragma unroll
    for (int r = 0; r < 2; r++) {
        int n  = tid + r * 256;              // complex index 0..511
        int j0 = 2 * n, j1 = 2 * n + 1;
        int p0 = base + j0;
        int p1 = base + j1;
        if (p0 < 0) p0 = -p0;
        if (p0 >= LSIG) p0 = 2 * LSIG - 2 - p0;
        if (p1 < 0) p1 = -p1;
        if (p1 >= LSIG) p1 = 2 * LSIG - 2 - p1;
        float v0 = xb[p0] * d_win[j0];
        float v1 = xb[p1] * d_win[j1];
        int rn = __brev(n) >> 23;            // 9-bit reversal
        s[rn] = make_float2(v0, v1);
    }
    __syncthreads();

    // 9 radix-2 DIT stages, 256 butterflies each
    #pragma unroll
    for (int st = 1; st <= 9; st++) {
        const int half = 1 << (st - 1);
        const int j    = tid & (half - 1);
        const int i0   = ((tid >> (st - 1)) << st) + j;
        const int i1   = i0 + half;
        const float2 w = d_tw[j << (9 - st)];
        float2 a = s[i0];
        float2 c = s[i1];
        float tr = c.x * w.x - c.y * w.y;
        float ti = c.x * w.y + c.y * w.x;
        s[i0] = make_float2(a.x + tr, a.y + ti);
        s[i1] = make_float2(a.x - tr, a.y - ti);
        __syncthreads();
    }

    // Hermitian untangle to rFFT bins k=1..512; store complex, coalesced.
    float2* sp = d_spec + ((size_t)b * NFRAMES + t) * FOUT;
    #pragma unroll
    for (int r = 0; r < 2; r++) {
        int k = tid + 1 + r * 256;           // 1..512
        float2 Zk = s[k & (NC - 1)];
        float2 Zm = s[(NC - k) & (NC - 1)];
        float ar = 0.5f * (Zk.x + Zm.x);
        float ai = 0.5f * (Zk.y - Zm.y);
        float br = 0.5f * (Zk.x - Zm.x);
        float bi = 0.5f * (Zk.y + Zm.y);
        float2 C = d_unt[k];
        float xr = ar + C.x * br - C.y * bi;
        float xi = ai + C.x * bi + C.y * br;
        // Nyquist bin is analytically real; reference stores imag = +0.0
        // exactly. Forcing it avoids noise-sign +/-pi flips in the phase.
        if (k == 512) xi = 0.0f;
        sp[k - 1] = make_float2(xr, xi);
    }
}

// Pass 2: tiled transpose + pointwise math.
// Tile: 32 freq x 32 out-frames (needs 33 frames of spectrum incl. halo).
// Reads frame-major scratch coalesced along k; writes out coalesced along t.
__global__ __launch_bounds__(256) void finalize_kernel(float* __restrict__ out)
{
    __shared__ float ph[33][33];   // [frame - t0][k - (f0+1)]
    __shared__ float mg[32][33];   // [frame-1 - t0][k - (f0+1)]
    const int tx = threadIdx.x & 31;
    const int ty = threadIdx.x >> 5;          // 0..7
    const int t0 = blockIdx.x * 32;           // 0..2016 (output t base)
    const int f0 = blockIdx.y * 32;           // 0..480  (output f base)
    const int b  = blockIdx.z;

    const float2* sp = d_spec + (size_t)b * NFRAMES * FOUT;
    for (int j = ty; j < 33; j += 8) {
        float2 v = sp[(size_t)(t0 + j) * FOUT + f0 + tx];
        ph[j][tx] = atan2f(v.y, v.x);
        if (j >= 1) {
            float m2 = v.x * v.x + v.y * v.y;
            mg[j - 1][tx] = (0.5f * logf(fmaxf(m2, 1e-14f)) + 17.0f) * (1.0f / 23.0f);
        }
    }
    __syncthreads();

    const float PI_F   = 3.14159274101257324f;   // float32(pi)
    const float TWO_PI = 6.28318548202514648f;   // float32(2*pi)

    for (int jj = ty; jj < 32; jj += 8) {
        int f = f0 + jj;
        size_t omag = (((size_t)b * 2 + 0) * FOUT + f) * TOUT + t0 + tx;
        size_t opha = (((size_t)b * 2 + 1) * FOUT + f) * TOUT + t0 + tx;

        out[omag] = mg[tx][jj];

        float p0 = ph[tx][jj];
        float p1 = ph[tx + 1][jj];
        float dd = p1 - p0;
        float res;
        if (fabsf(dd) < PI_F) {
            res = dd;
        } else {
            float r = fmodf(dd + PI_F, TWO_PI);
            if (r < 0.0f) r += TWO_PI;           // floor-mod like jnp.mod
            float ddmod = r - PI_F;
            if (ddmod == -PI_F && dd > 0.0f) ddmod = PI_F;
            res = ddmod;
        }
        out[opha] = res;
    }
}

extern "C" void kernel_launch(void* const* d_in, const int* in_sizes, int n_in,
                              void* d_out, int out_size)
{
    const float* x = (const float*)d_in[0];
    float* out = (float*)d_out;

    init_tables_kernel<<<1, 1024>>>();

    dim3 grid1(NFRAMES, NB);
    stft_frame_kernel<<<grid1, 256>>>(x);

    dim3 grid2(TOUT / 32, FOUT / 32, NB);     // (64, 16, 32)
    finalize_kernel<<<grid2, 256>>>(out);
}

// round 4
// speedup vs baseline: 1.0006x; 1.0006x over previous
#include <cuda_runtime.h>
#include <math.h>

// Problem constants
#define LSIG     524288
#define NFFT     1024
#define NC       512          // complex FFT size (rfft-via-cfft trick)
#define HOP      256
#define NFRAMES  2049
#define NB       32
#define FOUT     512          // freq bins 1..512
#define TOUT     2048         // frames 1..2048

// fp64-accurate tables (filled by init kernel each launch; deterministic)
__device__ float  d_win[NFFT];
__device__ float2 d_tw[256];     // exp(-2*pi*i*k/512), k=0..255
__device__ float2 d_unt[513];    // C_k = -i*exp(-i*pi*k/512) = (-sin, -cos)
// complex spectrum scratch, frame-major: [b][t][k-1], k=1..512  (268 MB)
__device__ float2 d_spec[(size_t)NB * NFRAMES * FOUT];

__global__ void init_tables_kernel() {
    int i = threadIdx.x;                      // 1024 threads
    const double PI = 3.14159265358979323846;
    d_win[i] = (float)(0.5 * (1.0 - cos(2.0 * PI * (double)i / 1024.0)));
    if (i < 256) {
        double th = -2.0 * PI * (double)i / 512.0;
        d_tw[i] = make_float2((float)cos(th), (float)sin(th));
    }
    if (i < 513) {
        double th = PI * (double)i / 512.0;
        d_unt[i] = make_float2((float)(-sin(th)), (float)(-cos(th)));
    }
}

// One CTA = one frame (b, t). 256 threads, 512-pt complex radix-2 FFT in smem.
// Writes the rFFT bins k=1..512 (complex) to frame-major scratch, coalesced.
__global__ __launch_bounds__(256) void stft_frame_kernel(const float* __restrict__ x)
{
    __shared__ float2 s[NC];
    const int t   = blockIdx.x;     // 0..2048
    const int b   = blockIdx.y;     // 0..31
    const int tid = threadIdx.x;    // 0..255

    const float* xb = x + (size_t)b * LSIG;
    const int base = t * HOP - (NFFT / 2);   // padded start - pad

    // Load 2 complex points (4 real samples) w/ reflect pad + window,
    // stored bit-reversed for DIT.
    #pragma unroll
    for (int r = 0; r < 2; r++) {
        int n  = tid + r * 256;              // complex index 0..511
        int j0 = 2 * n, j1 = 2 * n + 1;
        int p0 = base + j0;
        int p1 = base + j1;
        if (p0 < 0) p0 = -p0;
        if (p0 >= LSIG) p0 = 2 * LSIG - 2 - p0;
        if (p1 < 0) p1 = -p1;
        if (p1 >= LSIG) p1 = 2 * LSIG - 2 - p1;
        float v0 = xb[p0] * d_win[j0];
        float v1 = xb[p1] * d_win[j1];
        int rn = __brev(n) >> 23;            // 9-bit reversal
        s[rn] = make_float2(v0, v1);
    }
    __syncthreads();

    // 9 radix-2 DIT stages, 256 butterflies each
    #pragma unroll
    for (int st = 1; st <= 9; st++) {
        const int half = 1 << (st - 1);
        const int j    = tid & (half - 1);
        const int i0   = ((tid >> (st - 1)) << st) + j;
        const int i1   = i0 + half;
        const float2 w = d_tw[j << (9 - st)];
        float2 a = s[i0];
        float2 c = s[i1];
        float tr = c.x * w.x - c.y * w.y;
        float ti = c.x * w.y + c.y * w.x;
        s[i0] = make_float2(a.x + tr, a.y + ti);
        s[i1] = make_float2(a.x - tr, a.y - ti);
        __syncthreads();
    }

    // Hermitian untangle to rFFT bins k=1..512; store complex, coalesced.
    float2* sp = d_spec + ((size_t)b * NFRAMES + t) * FOUT;
    #pragma unroll
    for (int r = 0; r < 2; r++) {
        int k = tid + 1 + r * 256;           // 1..512
        float2 Zk = s[k & (NC - 1)];
        float2 Zm = s[(NC - k) & (NC - 1)];
        float ar = 0.5f * (Zk.x + Zm.x);
        float ai = 0.5f * (Zk.y - Zm.y);
        float br = 0.5f * (Zk.x - Zm.x);
        float bi = 0.5f * (Zk.y + Zm.y);
        float2 C = d_unt[k];
        float xr = ar + C.x * br - C.y * bi;
        float xi = ai + C.x * bi + C.y * br;
        // Nyquist bin is analytically real; reference stores imag = +0.0
        // exactly. Forcing it avoids noise-sign +/-pi flips in the phase.
        if (k == 512) xi = 0.0f;
        sp[k - 1] = make_float2(xr, xi);
    }
}

// Pass 2: tiled transpose + pointwise math.
// Tile: 32 freq x 32 out-frames (needs 33 frames of spectrum incl. halo).
// Reads frame-major scratch coalesced along k; writes out coalesced along t.
__global__ __launch_bounds__(256) void finalize_kernel(float* __restrict__ out)
{
    __shared__ float ph[33][33];   // [frame - t0][k - (f0+1)]
    __shared__ float mg[32][33];   // [frame-1 - t0][k - (f0+1)]
    const int tx = threadIdx.x & 31;
    const int ty = threadIdx.x >> 5;          // 0..7
    const int t0 = blockIdx.x * 32;           // 0..2016 (output t base)
    const int f0 = blockIdx.y * 32;           // 0..480  (output f base)
    const int b  = blockIdx.z;

    const float2* sp = d_spec + (size_t)b * NFRAMES * FOUT;
    for (int j = ty; j < 33; j += 8) {
        float2 v = sp[(size_t)(t0 + j) * FOUT + f0 + tx];
        ph[j][tx] = atan2f(v.y, v.x);
        if (j >= 1) {
            float m2 = v.x * v.x + v.y * v.y;
            mg[j - 1][tx] = (0.5f * logf(fmaxf(m2, 1e-14f)) + 17.0f) * (1.0f / 23.0f);
        }
    }
    __syncthreads();

    const float PI_F   = 3.14159274101257324f;   // float32(pi)
    const float TWO_PI = 6.28318548202514648f;   // float32(2*pi)

    for (int jj = ty; jj < 32; jj += 8) {
        int f = f0 + jj;
        size_t omag = (((size_t)b * 2 + 0) * FOUT + f) * TOUT + t0 + tx;
        size_t opha = (((size_t)b * 2 + 1) * FOUT + f) * TOUT + t0 + tx;

        out[omag] = mg[tx][jj];

        float p0 = ph[tx][jj];
        float p1 = ph[tx + 1][jj];
        float dd = p1 - p0;
        float res;
        if (fabsf(dd) < PI_F) {
            res = dd;
        } else {
            float r = fmodf(dd + PI_F, TWO_PI);
            if (r < 0.0f) r += TWO_PI;           // floor-mod like jnp.mod
            float ddmod = r - PI_F;
            if (ddmod == -PI_F && dd > 0.0f) ddmod = PI_F;
            res = ddmod;
        }
        out[opha] = res;
    }
}

extern "C" void kernel_launch(void* const* d_in, const int* in_sizes, int n_in,
                              void* d_out, int out_size)
{
    const float* x = (const float*)d_in[0];
    float* out = (float*)d_out;

    init_tables_kernel<<<1, 1024>>>();

    dim3 grid1(NFRAMES, NB);
    stft_frame_kernel<<<grid1, 256>>>(x);

    dim3 grid2(TOUT / 32, FOUT / 32, NB);     // (64, 16, 32)
    finalize_kernel<<<grid2, 256>>>(out);
}

// round 5
// speedup vs baseline: 1.0098x; 1.0092x over previous
#include <cuda_runtime.h>
#include <math.h>

// Problem constants
#define LSIG     524288
#define NFFT     1024
#define NC       512          // complex FFT size (rfft-via-cfft trick)
#define HOP      256
#define NFRAMES  2049
#define NB       32
#define FOUT     512          // freq bins 1..512
#define TOUT     2048         // frames 1..2048
#define FPB      8            // output frames per block

// fp64-accurate tables (filled by init kernel each launch; deterministic)
__device__ float  d_win[NFFT];
__device__ float2 d_tw[256];     // exp(-2*pi*i*k/512), k=0..255
__device__ float2 d_unt[513];    // C_k = -i*exp(-i*pi*k/512) = (-sin, -cos)

__global__ void init_tables_kernel() {
    int i = blockIdx.x * 128 + threadIdx.x;   // 8 blocks x 128 = 0..1023
    const double PI = 3.14159265358979323846;
    d_win[i] = (float)(0.5 * (1.0 - cos(2.0 * PI * (double)i / 1024.0)));
    if (i < 256) {
        double th = -2.0 * PI * (double)i / 512.0;
        d_tw[i] = make_float2((float)cos(th), (float)sin(th));
    }
    if (i < 513) {
        double th = PI * (double)i / 512.0;
        d_unt[i] = make_float2((float)(-sin(th)), (float)(-cos(th)));
    }
}

// Fused kernel. One CTA = (b, group of 8 output frames).
// Computes 9 consecutive frame FFTs (t = 8g .. 8g+8) sequentially in one
// 4KB smem buffer, stashes phase (9 frames) and log-mag (8 frames) in smem,
// then writes both output channels with float4 stores (coalesced along t).
// All per-element FP arithmetic is bit-identical to the R2 passing kernel.
__global__ __launch_bounds__(256) void stft_fused_kernel(
    const float* __restrict__ x, float* __restrict__ out)
{
    __shared__ float2 s[NC];
    __shared__ float  ph[FPB + 1][FOUT + 1];   // raw phase, frames 8g..8g+8
    __shared__ float  mg[FPB][FOUT + 1];       // log-mag,  frames 8g+1..8g+8

    const int g   = blockIdx.x;     // 0..255
    const int b   = blockIdx.y;     // 0..31
    const int tid = threadIdx.x;    // 0..255

    const float* xb = x + (size_t)b * LSIG;

    for (int f = 0; f <= FPB; f++) {
        const int t    = FPB * g + f;            // spectrum frame 0..2048
        const int base = t * HOP - (NFFT / 2);

        // Load 2 complex points (4 real samples) w/ reflect pad + window,
        // stored bit-reversed for DIT.
        #pragma unroll
        for (int r = 0; r < 2; r++) {
            int n  = tid + r * 256;              // complex index 0..511
            int j0 = 2 * n, j1 = 2 * n + 1;
            int p0 = base + j0;
            int p1 = base + j1;
            if (p0 < 0) p0 = -p0;
            if (p0 >= LSIG) p0 = 2 * LSIG - 2 - p0;
            if (p1 < 0) p1 = -p1;
            if (p1 >= LSIG) p1 = 2 * LSIG - 2 - p1;
            float v0 = xb[p0] * d_win[j0];
            float v1 = xb[p1] * d_win[j1];
            int rn = __brev(n) >> 23;            // 9-bit reversal
            s[rn] = make_float2(v0, v1);
        }
        __syncthreads();

        // 9 radix-2 DIT stages, 256 butterflies each
        #pragma unroll
        for (int st = 1; st <= 9; st++) {
            const int half = 1 << (st - 1);
            const int j    = tid & (half - 1);
            const int i0   = ((tid >> (st - 1)) << st) + j;
            const int i1   = i0 + half;
            const float2 w = d_tw[j << (9 - st)];
            float2 a = s[i0];
            float2 c = s[i1];
            float tr = c.x * w.x - c.y * w.y;
            float ti = c.x * w.y + c.y * w.x;
            s[i0] = make_float2(a.x + tr, a.y + ti);
            s[i1] = make_float2(a.x - tr, a.y - ti);
            __syncthreads();
        }

        // Hermitian untangle to rFFT bins k=1..512; phase + log-mag to smem.
        #pragma unroll
        for (int r = 0; r < 2; r++) {
            int k = tid + 1 + r * 256;           // 1..512
            float2 Zk = s[k & (NC - 1)];
            float2 Zm = s[(NC - k) & (NC - 1)];
            float ar = 0.5f * (Zk.x + Zm.x);
            float ai = 0.5f * (Zk.y - Zm.y);
            float br = 0.5f * (Zk.x - Zm.x);
            float bi = 0.5f * (Zk.y + Zm.y);
            float2 C = d_unt[k];
            float xr = ar + C.x * br - C.y * bi;
            float xi = ai + C.x * bi + C.y * br;
            // Nyquist bin is analytically real; reference stores imag = +0.0.
            if (k == 512) xi = 0.0f;
            ph[f][k - 1] = atan2f(xi, xr);
            if (f >= 1) {
                float m2 = xr * xr + xi * xi;
                mg[f - 1][k - 1] =
                    (0.5f * logf(fmaxf(m2, 1e-14f)) + 17.0f) * (1.0f / 23.0f);
            }
        }
        __syncthreads();   // protect s (next load) and ph/mg (writeback)
    }

    // Writeback: thread handles bins fo = tid and tid+256; 8 consecutive t's
    // each -> two float4 stores per channel, 32B-sector aligned (8g*4B).
    const float PI_F   = 3.14159274101257324f;   // float32(pi)
    const float TWO_PI = 6.28318548202514648f;   // float32(2*pi)

    #pragma unroll
    for (int r = 0; r < 2; r++) {
        int fo = tid + r * 256;                  // output freq 0..511
        size_t omag = (((size_t)b * 2 + 0) * FOUT + fo) * TOUT + FPB * g;
        size_t opha = (((size_t)b * 2 + 1) * FOUT + fo) * TOUT + FPB * g;

        float m[FPB], p[FPB];
        #pragma unroll
        for (int j = 0; j < FPB; j++) {
            m[j] = mg[j][fo];
            float p0 = ph[j][fo];
            float p1 = ph[j + 1][fo];
            float dd = p1 - p0;
            float res;
            if (fabsf(dd) < PI_F) {
                res = dd;
            } else {
                float rr = fmodf(dd + PI_F, TWO_PI);
                if (rr < 0.0f) rr += TWO_PI;     // floor-mod like jnp.mod
                float ddmod = rr - PI_F;
                if (ddmod == -PI_F && dd > 0.0f) ddmod = PI_F;
                res = ddmod;
            }
            p[j] = res;
        }
        *reinterpret_cast<float4*>(out + omag) =
            make_float4(m[0], m[1], m[2], m[3]);
        *reinterpret_cast<float4*>(out + omag + 4) =
            make_float4(m[4], m[5], m[6], m[7]);
        *reinterpret_cast<float4*>(out + opha) =
            make_float4(p[0], p[1], p[2], p[3]);
        *reinterpret_cast<float4*>(out + opha + 4) =
            make_float4(p[4], p[5], p[6], p[7]);
    }
}

extern "C" void kernel_launch(void* const* d_in, const int* in_sizes, int n_in,
                              void* d_out, int out_size)
{
    const float* x = (const float*)d_in[0];
    float* out = (float*)d_out;

    init_tables_kernel<<<8, 128>>>();

    dim3 grid(TOUT / FPB, NB);     // (256, 32)
    stft_fused_kernel<<<grid, 256>>>(x, out);
}

// round 8
// speedup vs baseline: 1.6428x; 1.6268x over previous
#include <cuda_runtime.h>
#include <math.h>

// Problem constants
#define LSIG     524288
#define NFFT     1024
#define NC       512
#define HOP      256
#define NB       32
#define FOUT     512
#define TOUT     2048
#define FPB      8            // output frames per block
#define PADBUF   576          // 512 + 64 pad (9-word rows)

// fp64-accurate tables
__device__ float  d_win[NFFT];
__device__ float2 d_tw[256];     // exp(-2*pi*i*k/512)
__device__ float2 d_unt[513];    // -i*exp(-i*pi*k/512)

__global__ void init_tables_kernel() {
    int i = blockIdx.x * 128 + threadIdx.x;   // 8 x 128 = 0..1023
    const double PI = 3.14159265358979323846;
    d_win[i] = (float)(0.5 * (1.0 - cos(2.0 * PI * (double)i / 1024.0)));
    if (i < 256) {
        double th = -2.0 * PI * (double)i / 512.0;
        d_tw[i] = make_float2((float)cos(th), (float)sin(th));
    }
    if (i < 513) {
        double th = PI * (double)i / 512.0;
        d_unt[i] = make_float2((float)(-sin(th)), (float)(-cos(th)));
    }
}

// Butterfly identical to the radix-2 reference: a=lower, c=upper.
#define BFLY(p, qq, w) do {                                   \
    float tr = xr[qq] * (w).x - xi[qq] * (w).y;               \
    float ti = xr[qq] * (w).y + xi[qq] * (w).x;               \
    float ax = xr[p], ay = xi[p];                             \
    xr[p]  = ax + tr;  xi[p]  = ay + ti;                      \
    xr[qq] = ax - tr;  xi[qq] = ay - ti;                      \
} while (0)

// One CTA = (b, group of 8 output frames). 4 sub-groups of 64 threads each
// run one 512-pt FFT with 8 complex points/thread in registers; smem only
// for 3 stage-exchanges (bank-conflict-free padded addressing).
__global__ __launch_bounds__(256) void stft_fused_kernel(
    const float* __restrict__ x, float* __restrict__ out)
{
    extern __shared__ float sm[];
    const int tid = threadIdx.x;
    const int q   = tid >> 6;        // group 0..3
    const int gt  = tid & 63;        // thread in group
    const int g   = blockIdx.x;      // 0..255
    const int b   = blockIdx.y;      // 0..31

    float* Ar = sm + q * (4 * PADBUF);
    float* Ai = Ar + PADBUF;
    float* Br = Ai + PADBUF;
    float* Bi = Br + PADBUF;
    float* ph = sm + 4 * (4 * PADBUF);          // [9][513]
    float* mg = ph + 9 * 513;                   // [8][513]

    const float* xb = x + (size_t)b * LSIG;

    for (int r = 0; r < 3; r++) {
        const int f = 4 * r + q;                 // spectrum slot 0..8
        const bool active = (f <= FPB);
        const int t    = FPB * g + f;
        const int base = t * HOP - (NFFT / 2);

        // ---- load: windowed input, linear complex order -> B buffers ----
        if (active) {
            #pragma unroll
            for (int jj = 0; jj < 8; jj++) {
                int n  = 64 * jj + gt;           // complex index
                int j0 = 2 * n, j1 = 2 * n + 1;
                int p0 = base + j0;
                int p1 = base + j1;
                if (p0 < 0) p0 = -p0;
                if (p0 >= LSIG) p0 = 2 * LSIG - 2 - p0;
                if (p1 < 0) p1 = -p1;
                if (p1 >= LSIG) p1 = 2 * LSIG - 2 - p1;
                Br[n] = xb[p0] * d_win[j0];
                Bi[n] = xb[p1] * d_win[j1];
            }
        }
        __syncthreads();

        float xr[8], xi[8];

        // ---- phase A: gather bit-reversed, stages 1-3 in regs ----
        if (active) {
            const int br6 = __brev(gt) >> 26;
            const int BR3[8] = {0, 4, 2, 6, 1, 5, 3, 7};
            #pragma unroll
            for (int j = 0; j < 8; j++) {
                int n = (BR3[j] << 6) | br6;
                xr[j] = Br[n];
                xi[j] = Bi[n];
            }
            // stage 1 (half=1): tw = d_tw[0]
            { float2 w = d_tw[0];
              BFLY(0,1,w); BFLY(2,3,w); BFLY(4,5,w); BFLY(6,7,w); }
            // stage 2 (half=2)
            { float2 w0 = d_tw[0], w1 = d_tw[128];
              BFLY(0,2,w0); BFLY(1,3,w1); BFLY(4,6,w0); BFLY(5,7,w1); }
            // stage 3 (half=4)
            { float2 w0 = d_tw[0], w1 = d_tw[64], w2 = d_tw[128], w3 = d_tw[192];
              BFLY(0,4,w0); BFLY(1,5,w1); BFLY(2,6,w2); BFLY(3,7,w3); }
            // write: index i=8*gt+j at padded addr 9*gt+j
            #pragma unroll
            for (int j = 0; j < 8; j++) {
                Ar[9 * gt + j] = xr[j];
                Ai[9 * gt + j] = xi[j];
            }
        }
        __syncthreads();

        // ---- phase B: i = 64H + 8j + L, stages 4-6 ----
        if (active) {
            const int H = gt >> 3, L = gt & 7;
            #pragma unroll
            for (int j = 0; j < 8; j++) {
                int a = 72 * H + 9 * j + L;      // addr1(64H+8j+L)
                xr[j] = Ar[a];
                xi[j] = Ai[a];
            }
            // stage 4 (half=8): tw idx = L<<5 for all pairs
            { float2 w = d_tw[L << 5];
              BFLY(0,1,w); BFLY(2,3,w); BFLY(4,5,w); BFLY(6,7,w); }
            // stage 5 (half=16)
            { float2 w0 = d_tw[L << 4], w1 = d_tw[(8 + L) << 4];
              BFLY(0,2,w0); BFLY(1,3,w1); BFLY(4,6,w0); BFLY(5,7,w1); }
            // stage 6 (half=32)
            { float2 w0 = d_tw[L << 3],        w1 = d_tw[(8 + L) << 3];
              float2 w2 = d_tw[(16 + L) << 3], w3 = d_tw[(24 + L) << 3];
              BFLY(0,4,w0); BFLY(1,5,w1); BFLY(2,6,w2); BFLY(3,7,w3); }
            // write: i = 64H+8j+L at addr2 = 9*(i&63) + (i>>6) = 72j+9L+H
            #pragma unroll
            for (int j = 0; j < 8; j++) {
                Br[72 * j + 9 * L + H] = xr[j];
                Bi[72 * j + 9 * L + H] = xi[j];
            }
        }
        __syncthreads();

        // ---- phase C: i = 64j + gt, stages 7-9, final natural order ----
        if (active) {
            #pragma unroll
            for (int j = 0; j < 8; j++) {
                int a = 9 * gt + j;              // addr2(64j+gt)
                xr[j] = Br[a];
                xi[j] = Bi[a];
            }
            // stage 7 (half=64)
            { float2 w = d_tw[gt << 2];
              BFLY(0,1,w); BFLY(2,3,w); BFLY(4,5,w); BFLY(6,7,w); }
            // stage 8 (half=128)
            { float2 w0 = d_tw[gt << 1], w1 = d_tw[(64 + gt) << 1];
              BFLY(0,2,w0); BFLY(1,3,w1); BFLY(4,6,w0); BFLY(5,7,w1); }
            // stage 9 (half=256)
            { float2 w0 = d_tw[gt],       w1 = d_tw[64 + gt];
              float2 w2 = d_tw[128 + gt], w3 = d_tw[192 + gt];
              BFLY(0,4,w0); BFLY(1,5,w1); BFLY(2,6,w2); BFLY(3,7,w3); }
            // final spectrum Z[64j+gt], plain layout in A buffers
            #pragma unroll
            for (int j = 0; j < 8; j++) {
                Ar[64 * j + gt] = xr[j];
                Ai[64 * j + gt] = xi[j];
            }
        }
        __syncthreads();

        // ---- untangle + phase/log-mag to smem (verbatim R4 math) ----
        if (active) {
            #pragma unroll
            for (int rr = 0; rr < 8; rr++) {
                int k = 64 * rr + gt + 1;        // 1..512
                int km = (NC - k) & (NC - 1);
                float2 Zk = make_float2(Ar[k & (NC - 1)], Ai[k & (NC - 1)]);
                float2 Zm = make_float2(Ar[km], Ai[km]);
                float ar = 0.5f * (Zk.x + Zm.x);
                float ai = 0.5f * (Zk.y - Zm.y);
                float br = 0.5f * (Zk.x - Zm.x);
                float bi = 0.5f * (Zk.y + Zm.y);
                float2 C = d_unt[k];
                float vr = ar + C.x * br - C.y * bi;
                float vi = ai + C.x * bi + C.y * br;
                if (k == 512) vi = 0.0f;         // Nyquist analytically real
                ph[f * 513 + (k - 1)] = atan2f(vi, vr);
                if (f >= 1) {
                    float m2 = vr * vr + vi * vi;
                    mg[(f - 1) * 513 + (k - 1)] =
                        (0.5f * logf(fmaxf(m2, 1e-14f)) + 17.0f) * (1.0f / 23.0f);
                }
            }
        }
        __syncthreads();
    }

    // ---- writeback: per-thread 8 consecutive t's, float4 stores ----
    const float PI_F   = 3.14159274101257324f;
    const float TWO_PI = 6.28318548202514648f;

    #pragma unroll
    for (int r = 0; r < 2; r++) {
        int fo = tid + r * 256;                  // output freq 0..511
        size_t omag = (((size_t)b * 2 + 0) * FOUT + fo) * TOUT + FPB * g;
        size_t opha = (((size_t)b * 2 + 1) * FOUT + fo) * TOUT + FPB * g;

        float m[FPB], p[FPB];
        #pragma unroll
        for (int j = 0; j < FPB; j++) {
            m[j] = mg[j * 513 + fo];
            float p0 = ph[j * 513 + fo];
            float p1 = ph[(j + 1) * 513 + fo];
            float dd = p1 - p0;
            float res;
            if (fabsf(dd) < PI_F) {
                res = dd;
            } else {
                float rr = fmodf(dd + PI_F, TWO_PI);
                if (rr < 0.0f) rr += TWO_PI;
                float ddmod = rr - PI_F;
                if (ddmod == -PI_F && dd > 0.0f) ddmod = PI_F;
                res = ddmod;
            }
            p[j] = res;
        }
        *reinterpret_cast<float4*>(out + omag) =
            make_float4(m[0], m[1], m[2], m[3]);
        *reinterpret_cast<float4*>(out + omag + 4) =
            make_float4(m[4], m[5], m[6], m[7]);
        *reinterpret_cast<float4*>(out + opha) =
            make_float4(p[0], p[1], p[2], p[3]);
        *reinterpret_cast<float4*>(out + opha + 4) =
            make_float4(p[4], p[5], p[6], p[7]);
    }
}

extern "C" void kernel_launch(void* const* d_in, const int* in_sizes, int n_in,
                              void* d_out, int out_size)
{
    const float* x = (const float*)d_in[0];
    float* out = (float*)d_out;

    // 4 groups * 4 arrays * 576 + ph 9*513 + mg 8*513 floats
    const int smem_bytes = (4 * 4 * PADBUF + 9 * 513 + 8 * 513) * 4;
    cudaFuncSetAttribute(stft_fused_kernel,
                         cudaFuncAttributeMaxDynamicSharedMemorySize,
                         smem_bytes);

    init_tables_kernel<<<8, 128>>>();

    dim3 grid(TOUT / FPB, NB);     // (256, 32)
    stft_fused_kernel<<<grid, 256, smem_bytes>>>(x, out);
}

// round 9
// speedup vs baseline: 1.7647x; 1.0742x over previous
#include <cuda_runtime.h>
#include <math.h>

// Problem constants
#define LSIG     524288
#define NFFT     1024
#define NC       512
#define HOP      256
#define NB       32
#define FOUT     512
#define TOUT     2048
#define FPB      8            // output frames per block
#define PADBUF   576          // 512 + 64 pad (9-word rows)

// fp64-accurate tables
__device__ float  d_win[NFFT];
__device__ float2 d_tw[256];     // exp(-2*pi*i*k/512)
__device__ float2 d_unt[513];    // -i*exp(-i*pi*k/512)

__global__ void init_tables_kernel() {
    int i = blockIdx.x * 128 + threadIdx.x;   // 8 x 128 = 0..1023
    const double PI = 3.14159265358979323846;
    d_win[i] = (float)(0.5 * (1.0 - cos(2.0 * PI * (double)i / 1024.0)));
    if (i < 256) {
        double th = -2.0 * PI * (double)i / 512.0;
        d_tw[i] = make_float2((float)cos(th), (float)sin(th));
    }
    if (i < 513) {
        double th = PI * (double)i / 512.0;
        d_unt[i] = make_float2((float)(-sin(th)), (float)(-cos(th)));
    }
}

// Butterfly identical to the radix-2 reference: a=lower, c=upper.
#define BFLY(p, qq, w) do {                                   \
    float tr = xr[qq] * (w).x - xi[qq] * (w).y;               \
    float ti = xr[qq] * (w).y + xi[qq] * (w).x;               \
    float ax = xr[p], ay = xi[p];                             \
    xr[p]  = ax + tr;  xi[p]  = ay + ti;                      \
    xr[qq] = ax - tr;  xi[qq] = ay - ti;                      \
} while (0)

// Intra-group barrier: 64 threads (2 warps), named barrier q+1.
#define GBAR() asm volatile("bar.sync %0, 64;" :: "r"(q + 1) : "memory")

// One CTA = (b, group of 8 output frames). 4 sub-groups of 64 threads each
// run one 512-pt FFT with 8 complex points/thread in registers; smem only
// for 3 stage-exchanges. All sync inside the FFT is per-group (named
// barriers); one full __syncthreads() before the cross-group writeback.
__global__ __launch_bounds__(256) void stft_fused_kernel(
    const float* __restrict__ x, float* __restrict__ out)
{
    extern __shared__ float sm[];
    const int tid = threadIdx.x;
    const int q   = tid >> 6;        // group 0..3
    const int gt  = tid & 63;        // thread in group
    const int g   = blockIdx.x;      // 0..255
    const int b   = blockIdx.y;      // 0..31

    float* Ar = sm + q * (4 * PADBUF);
    float* Ai = Ar + PADBUF;
    float* Br = Ai + PADBUF;
    float* Bi = Br + PADBUF;
    float* ph = sm + 4 * (4 * PADBUF);          // [9][513]
    float* mg = ph + 9 * 513;                   // [8][513]

    const float* xb = x + (size_t)b * LSIG;

    for (int r = 0; r < 3; r++) {
        const int f = 4 * r + q;                 // spectrum slot 0..8
        const bool active = (f <= FPB);
        const int t    = FPB * g + f;
        const int base = t * HOP - (NFFT / 2);

        if (active) {
            // ---- load: windowed input, linear complex order -> B ----
            #pragma unroll
            for (int jj = 0; jj < 8; jj++) {
                int n  = 64 * jj + gt;           // complex index
                int j0 = 2 * n, j1 = 2 * n + 1;
                int p0 = base + j0;
                int p1 = base + j1;
                if (p0 < 0) p0 = -p0;
                if (p0 >= LSIG) p0 = 2 * LSIG - 2 - p0;
                if (p1 < 0) p1 = -p1;
                if (p1 >= LSIG) p1 = 2 * LSIG - 2 - p1;
                Br[n] = xb[p0] * d_win[j0];
                Bi[n] = xb[p1] * d_win[j1];
            }
            GBAR();

            float xr[8], xi[8];

            // ---- phase A: gather bit-reversed, stages 1-3 in regs ----
            const int br6 = __brev(gt) >> 26;
            const int BR3[8] = {0, 4, 2, 6, 1, 5, 3, 7};
            #pragma unroll
            for (int j = 0; j < 8; j++) {
                int n = (BR3[j] << 6) | br6;
                xr[j] = Br[n];
                xi[j] = Bi[n];
            }
            { float2 w = d_tw[0];
              BFLY(0,1,w); BFLY(2,3,w); BFLY(4,5,w); BFLY(6,7,w); }
            { float2 w0 = d_tw[0], w1 = d_tw[128];
              BFLY(0,2,w0); BFLY(1,3,w1); BFLY(4,6,w0); BFLY(5,7,w1); }
            { float2 w0 = d_tw[0], w1 = d_tw[64], w2 = d_tw[128], w3 = d_tw[192];
              BFLY(0,4,w0); BFLY(1,5,w1); BFLY(2,6,w2); BFLY(3,7,w3); }
            #pragma unroll
            for (int j = 0; j < 8; j++) {
                Ar[9 * gt + j] = xr[j];
                Ai[9 * gt + j] = xi[j];
            }
            GBAR();

            // ---- phase B: i = 64H + 8j + L, stages 4-6 ----
            const int H = gt >> 3, L = gt & 7;
            #pragma unroll
            for (int j = 0; j < 8; j++) {
                int a = 72 * H + 9 * j + L;      // addr1(64H+8j+L)
                xr[j] = Ar[a];
                xi[j] = Ai[a];
            }
            { float2 w = d_tw[L << 5];
              BFLY(0,1,w); BFLY(2,3,w); BFLY(4,5,w); BFLY(6,7,w); }
            { float2 w0 = d_tw[L << 4], w1 = d_tw[(8 + L) << 4];
              BFLY(0,2,w0); BFLY(1,3,w1); BFLY(4,6,w0); BFLY(5,7,w1); }
            { float2 w0 = d_tw[L << 3],        w1 = d_tw[(8 + L) << 3];
              float2 w2 = d_tw[(16 + L) << 3], w3 = d_tw[(24 + L) << 3];
              BFLY(0,4,w0); BFLY(1,5,w1); BFLY(2,6,w2); BFLY(3,7,w3); }
            #pragma unroll
            for (int j = 0; j < 8; j++) {
                Br[72 * j + 9 * L + H] = xr[j];  // addr2(64H+8j+L)
                Bi[72 * j + 9 * L + H] = xi[j];
            }
            GBAR();

            // ---- phase C: i = 64j + gt, stages 7-9, natural order ----
            #pragma unroll
            for (int j = 0; j < 8; j++) {
                int a = 9 * gt + j;              // addr2(64j+gt)
                xr[j] = Br[a];
                xi[j] = Bi[a];
            }
            { float2 w = d_tw[gt << 2];
              BFLY(0,1,w); BFLY(2,3,w); BFLY(4,5,w); BFLY(6,7,w); }
            { float2 w0 = d_tw[gt << 1], w1 = d_tw[(64 + gt) << 1];
              BFLY(0,2,w0); BFLY(1,3,w1); BFLY(4,6,w0); BFLY(5,7,w1); }
            { float2 w0 = d_tw[gt],       w1 = d_tw[64 + gt];
              float2 w2 = d_tw[128 + gt], w3 = d_tw[192 + gt];
              BFLY(0,4,w0); BFLY(1,5,w1); BFLY(2,6,w2); BFLY(3,7,w3); }
            #pragma unroll
            for (int j = 0; j < 8; j++) {
                Ar[64 * j + gt] = xr[j];
                Ai[64 * j + gt] = xi[j];
            }
            GBAR();

            // ---- untangle + phase/log-mag to smem (phase math verbatim) --
            #pragma unroll
            for (int rr = 0; rr < 8; rr++) {
                int k = 64 * rr + gt + 1;        // 1..512
                int km = (NC - k) & (NC - 1);
                float2 Zk = make_float2(Ar[k & (NC - 1)], Ai[k & (NC - 1)]);
                float2 Zm = make_float2(Ar[km], Ai[km]);
                float ar = 0.5f * (Zk.x + Zm.x);
                float ai = 0.5f * (Zk.y - Zm.y);
                float br = 0.5f * (Zk.x - Zm.x);
                float bi = 0.5f * (Zk.y + Zm.y);
                float2 C = d_unt[k];
                float vr = ar + C.x * br - C.y * bi;
                float vi = ai + C.x * bi + C.y * br;
                if (k == 512) vi = 0.0f;         // Nyquist analytically real
                ph[f * 513 + (k - 1)] = atan2f(vi, vr);
                if (f >= 1) {
                    float m2 = vr * vr + vi * vi;
                    mg[(f - 1) * 513 + (k - 1)] =
                        (0.5f * __logf(fmaxf(m2, 1e-14f)) + 17.0f) * (1.0f / 23.0f);
                }
            }
            // No barrier needed here: Ar next written in phase A of the
            // next round (after GBAR post-load); Br next written by the
            // next load (after GBAR post-C). ph/mg consumed only after
            // the full __syncthreads() below.
        }
    }

    __syncthreads();   // staging (ph/mg) is read across groups below

    // ---- writeback: per-thread 8 consecutive t's, float4 stores ----
    const float PI_F   = 3.14159274101257324f;
    const float TWO_PI = 6.28318548202514648f;

    #pragma unroll
    for (int r = 0; r < 2; r++) {
        int fo = tid + r * 256;                  // output freq 0..511
        size_t omag = (((size_t)b * 2 + 0) * FOUT + fo) * TOUT + FPB * g;
        size_t opha = (((size_t)b * 2 + 1) * FOUT + fo) * TOUT + FPB * g;

        float m[FPB], p[FPB];
        #pragma unroll
        for (int j = 0; j < FPB; j++) {
            m[j] = mg[j * 513 + fo];
            float p0 = ph[j * 513 + fo];
            float p1 = ph[(j + 1) * 513 + fo];
            float dd = p1 - p0;
            float res;
            if (fabsf(dd) < PI_F) {
                res = dd;
            } else {
                float rr = fmodf(dd + PI_F, TWO_PI);
                if (rr < 0.0f) rr += TWO_PI;
                float ddmod = rr - PI_F;
                if (ddmod == -PI_F && dd > 0.0f) ddmod = PI_F;
                res = ddmod;
            }
            p[j] = res;
        }
        *reinterpret_cast<float4*>(out + omag) =
            make_float4(m[0], m[1], m[2], m[3]);
        *reinterpret_cast<float4*>(out + omag + 4) =
            make_float4(m[4], m[5], m[6], m[7]);
        *reinterpret_cast<float4*>(out + opha) =
            make_float4(p[0], p[1], p[2], p[3]);
        *reinterpret_cast<float4*>(out + opha + 4) =
            make_float4(p[4], p[5], p[6], p[7]);
    }
}

extern "C" void kernel_launch(void* const* d_in, const int* in_sizes, int n_in,
                              void* d_out, int out_size)
{
    const float* x = (const float*)d_in[0];
    float* out = (float*)d_out;

    const int smem_bytes = (4 * 4 * PADBUF + 9 * 513 + 8 * 513) * 4;
    cudaFuncSetAttribute(stft_fused_kernel,
                         cudaFuncAttributeMaxDynamicSharedMemorySize,
                         smem_bytes);

    init_tables_kernel<<<8, 128>>>();

    dim3 grid(TOUT / FPB, NB);     // (256, 32)
    stft_fused_kernel<<<grid, 256, smem_bytes>>>(x, out);
}